// round 12
// baseline (speedup 1.0000x reference)
#include <cuda_runtime.h>
#include <cuda_bf16.h>
#include <cstdint>
#include <cstddef>

#define NR 16384
#define DX 1024
#define DH 2048

// ---------------- device scratch (no dynamic allocation allowed) -----------
__device__ __align__(16) __nv_bfloat16 g_Zb[(size_t)NR * 2048];     // [X1|X2]
__device__ __align__(16) __nv_bfloat16 g_Wst[(size_t)2048 * 2048];  // [W1h;-W2h]
__device__ __align__(16) __nv_bfloat16 g_W2hb[(size_t)1024 * 2048];
__device__ __align__(16) __nv_bfloat16 g_Wh1b[(size_t)2048 * 1024];
__device__ __align__(16) __nv_bfloat16 g_Wh2b[(size_t)2048 * 1024];
__device__ __align__(16) __nv_bfloat16 g_M12[(size_t)1024 * 1024];
__device__ __align__(16) __nv_bfloat16 g_M21[(size_t)1024 * 1024];
__device__ float g_b12[1024];
__device__ float g_b21[1024];
__device__ float g_db[2048];
__device__ float g_v[2048];
__device__ float g_c0[1];
__device__ float g_row1[NR];
__device__ float g_row2[NR];
__device__ float g_row3[NR];
__device__ float g_L4sq[NR];
__device__ int   g_mdone;

// ---------------- helpers --------------------------------------------------
__device__ __forceinline__ uint32_t smem_u32(const void* p) {
    uint32_t a;
    asm("{ .reg .u64 t; cvta.to.shared.u64 t, %1; cvt.u32.u64 %0, t; }"
        : "=r"(a) : "l"(p));
    return a;
}
__device__ __forceinline__ void cp16(uint32_t dst, const void* src) {
    uint64_t g;
    asm("cvta.to.global.u64 %0, %1;" : "=l"(g) : "l"(src));
    asm volatile("cp.async.cg.shared.global [%0], [%1], 16;"
                 :: "r"(dst), "l"(g) : "memory");
}
#define CP_COMMIT asm volatile("cp.async.commit_group;" ::: "memory")
#define CP_WAIT(n) asm volatile("cp.async.wait_group %0;" :: "n"(n) : "memory")

// ---------------- converts / init ------------------------------------------
__global__ void convz_kernel(const float* __restrict__ X1,
                             const float* __restrict__ X2) {
    int i = blockIdx.x * blockDim.x + threadIdx.x;
    int stride = gridDim.x * blockDim.x;
    for (; i < NR * 256; i += stride) {
        int r = i >> 8, c = (i & 255) * 4;
        float4 a = __ldcs((const float4*)&X1[(size_t)r * 1024 + c]);
        float4 b = __ldcs((const float4*)&X2[(size_t)r * 1024 + c]);
        __nv_bfloat162 a0 = __floats2bfloat162_rn(a.x, a.y);
        __nv_bfloat162 a1 = __floats2bfloat162_rn(a.z, a.w);
        __nv_bfloat162 b0 = __floats2bfloat162_rn(b.x, b.y);
        __nv_bfloat162 b1 = __floats2bfloat162_rn(b.z, b.w);
        size_t o = (size_t)r * 2048 + c;
        __stcs((uint32_t*)&g_Zb[o],        *(uint32_t*)&a0);
        __stcs((uint32_t*)&g_Zb[o + 2],    *(uint32_t*)&a1);
        __stcs((uint32_t*)&g_Zb[o + 1024], *(uint32_t*)&b0);
        __stcs((uint32_t*)&g_Zb[o + 1026], *(uint32_t*)&b1);
    }
}

__global__ void convw_kernel(const float* __restrict__ w1hW,
                             const float* __restrict__ w2hW,
                             const float* __restrict__ wh1W,
                             const float* __restrict__ wh2W) {
    const int NW = DX * DH / 4;
    int i = blockIdx.x * blockDim.x + threadIdx.x;
    int stride = gridDim.x * blockDim.x;
    for (; i < 4 * NW; i += stride) {
        int sel = i / NW;
        int idx = (i - sel * NW) * 4;
        const float* src = (sel == 0) ? w1hW : (sel == 1) ? w2hW
                          : (sel == 2) ? wh1W : wh2W;
        float4 v = __ldcs((const float4*)&src[idx]);
        __nv_bfloat162 lo = __floats2bfloat162_rn(v.x, v.y);
        __nv_bfloat162 hi = __floats2bfloat162_rn(v.z, v.w);
        if (sel == 0) {
            *(uint32_t*)&g_Wst[idx]     = *(uint32_t*)&lo;
            *(uint32_t*)&g_Wst[idx + 2] = *(uint32_t*)&hi;
        } else if (sel == 1) {
            __nv_bfloat162 nlo = __floats2bfloat162_rn(-v.x, -v.y);
            __nv_bfloat162 nhi = __floats2bfloat162_rn(-v.z, -v.w);
            *(uint32_t*)&g_Wst[(size_t)1024 * 2048 + idx]     = *(uint32_t*)&nlo;
            *(uint32_t*)&g_Wst[(size_t)1024 * 2048 + idx + 2] = *(uint32_t*)&nhi;
            *(uint32_t*)&g_W2hb[idx]     = *(uint32_t*)&lo;
            *(uint32_t*)&g_W2hb[idx + 2] = *(uint32_t*)&hi;
        } else {
            __nv_bfloat16* dst = (sel == 2) ? g_Wh1b : g_Wh2b;
            *(uint32_t*)&dst[idx]     = *(uint32_t*)&lo;
            *(uint32_t*)&dst[idx + 2] = *(uint32_t*)&hi;
        }
    }
}

__global__ void init_kernel(const float* __restrict__ b1h,
                            const float* __restrict__ b2h,
                            const float* __restrict__ bh1,
                            const float* __restrict__ bh2) {
    int i = blockIdx.x * blockDim.x + threadIdx.x;
    if (i == 0) g_mdone = 0;
    if (i < NR) { g_row1[i] = 0.f; g_row2[i] = 0.f; g_row3[i] = 0.f; }
    if (i < 2048) g_db[i] = b1h[i] - b2h[i];
    if (i < 1024) { g_b12[i] = bh2[i]; g_b21[i] = bh1[i]; }
}

__global__ void bcomp_kernel(const float* __restrict__ b1h,
                             const float* __restrict__ b2h,
                             const float* __restrict__ wh2W,
                             const float* __restrict__ wh1W) {
    const int sel = blockIdx.z;
    const float* bh = sel ? b2h : b1h;
    const float* W  = sel ? wh1W : wh2W;
    float* out = sel ? g_b21 : g_b12;
    int j = blockIdx.x * 256 + threadIdx.x;
    int k0 = blockIdx.y * 16;
    float s = 0.f;
    #pragma unroll
    for (int k = 0; k < 16; k++)
        s += bh[k0 + k] * W[(size_t)(k0 + k) * 1024 + j];
    atomicAdd(&out[j], s);
}

__global__ void vcomp_kernel(const float* __restrict__ W1h,
                             const float* __restrict__ W2h,
                             const float* __restrict__ who,
                             const float* __restrict__ b1h,
                             const float* __restrict__ b2h,
                             const float* __restrict__ whob) {
    int w = (blockIdx.x * blockDim.x + threadIdx.x) >> 5;
    int lane = threadIdx.x & 31;
    if (w > 2048) return;
    if (w == 2048) {
        float s = 0.f;
        for (int k = lane; k < 2048; k += 32)
            s += (b1h[k] + b2h[k]) * who[k];
        #pragma unroll
        for (int o = 16; o; o >>= 1) s += __shfl_xor_sync(0xffffffffu, s, o);
        if (lane == 0) g_c0[0] = s + whob[0];
        return;
    }
    const float* row = (w < 1024) ? &W1h[(size_t)w * 2048]
                                  : &W2h[(size_t)(w - 1024) * 2048];
    float s = 0.f;
    for (int k = lane; k < 2048; k += 32) s += row[k] * who[k];
    #pragma unroll
    for (int o = 16; o; o >>= 1) s += __shfl_xor_sync(0xffffffffu, s, o);
    if (lane == 0) g_v[w] = s;
}

// ---------------- single merged GEMM launch ---------------------------------
// bid 0..127    : M-tiles   C = A*B -> bf16 M12/M21 (K=2048, publish counter)
// bid 128..2175 : L3 tiles  row3 += sum (C + db)^2           (K=2048)
// bid 2176..4223: X tiles   row1/2 += sum (C + bias - Z)^2   (K=1024, gated)
__launch_bounds__(256, 2)
__global__ void gemm_all() {
    const int bid = blockIdx.x;
    const __nv_bfloat16 *A, *B;
    __nv_bfloat16* C = nullptr;
    float* R = nullptr;
    const float* bias = nullptr;
    int K, LDB, aoff = 0, xoff = 0, mode, bx, by;

    if (bid < 128) {
        int z = bid >> 6, t = bid & 63;
        bx = t & 7; by = t >> 3;
        A = z ? g_W2hb : g_Wst;  B = z ? g_Wh1b : g_Wh2b;
        C = z ? g_M21 : g_M12;
        K = 2048; LDB = 1024; mode = 0;
    } else if (bid < 2176) {
        int t = bid - 128;
        bx = t & 15; by = t >> 4;
        A = g_Zb; B = g_Wst; R = g_row3; bias = g_db;
        K = 2048; LDB = 2048; mode = 1;
    } else {
        int t = bid - 2176;
        int zz = t >> 10; t &= 1023;
        bx = t & 7; by = t >> 3;
        A = g_Zb; aoff = zz * 1024;
        B = zz ? g_M21 : g_M12; R = zz ? g_row2 : g_row1;
        bias = zz ? g_b21 : g_b12; xoff = zz ? 0 : 1024;
        K = 1024; LDB = 1024; mode = 2;
        // gate: all 128 M-tiles must have published M12/M21
        if (threadIdx.x == 0) {
            while (*(volatile int*)&g_mdone < 128) __nanosleep(200);
            __threadfence();
        }
        __syncthreads();
    }

    __shared__ __align__(16) __nv_bfloat16 smA[2][128][40];
    __shared__ __align__(16) __nv_bfloat16 smB[2][32][136];

    const int tid = threadIdx.x, lane = tid & 31, wid = tid >> 5;
    const int wm = wid >> 2, wn = wid & 3;
    const int brow = by * 128, bcol = bx * 128;

    float c[4][4][4];
    #pragma unroll
    for (int i = 0; i < 4; i++)
        #pragma unroll
        for (int j = 0; j < 4; j++)
            #pragma unroll
            for (int k = 0; k < 4; k++) c[i][j][k] = 0.f;

    auto loadA = [&](int st, int k0) {
        #pragma unroll
        for (int i = 0; i < 2; i++) {
            int id = tid + i * 256;
            int r = id >> 2, kc = (id & 3) * 8;
            cp16(smem_u32(&smA[st][r][kc]),
                 &A[(size_t)(brow + r) * 2048 + aoff + k0 + kc]);
        }
    };
    auto loadB = [&](int st, int k0) {
        #pragma unroll
        for (int i = 0; i < 2; i++) {
            int id = tid + i * 256;
            int r = id >> 4, nc = (id & 15) * 8;
            cp16(smem_u32(&smB[st][r][nc]),
                 &B[(size_t)(k0 + r) * LDB + bcol + nc]);
        }
    };

    loadA(0, 0); loadB(0, 0); CP_COMMIT;
    const int nk = K / 32;
    for (int kt = 0; kt < nk; kt++) {
        const int cur = kt & 1, nxt = cur ^ 1;
        if (kt + 1 < nk) { loadA(nxt, (kt + 1) * 32); loadB(nxt, (kt + 1) * 32);
                           CP_COMMIT; CP_WAIT(1); }
        else             { CP_WAIT(0); }
        __syncthreads();

        #pragma unroll
        for (int ks = 0; ks < 32; ks += 16) {
            uint32_t a[4][4];
            #pragma unroll
            for (int mt = 0; mt < 4; mt++) {
                uint32_t ad = smem_u32(
                    &smA[cur][wm * 64 + mt * 16 + (lane & 15)][ks + (lane >> 4) * 8]);
                asm volatile(
                    "ldmatrix.sync.aligned.m8n8.x4.shared.b16 {%0,%1,%2,%3},[%4];"
                    : "=r"(a[mt][0]), "=r"(a[mt][1]), "=r"(a[mt][2]), "=r"(a[mt][3])
                    : "r"(ad));
            }
            uint32_t b[2][4];
            #pragma unroll
            for (int np = 0; np < 2; np++) {
                uint32_t ad = smem_u32(
                    &smB[cur][ks + (lane & 15)][wn * 32 + np * 16 + (lane >> 4) * 8]);
                asm volatile(
                    "ldmatrix.sync.aligned.m8n8.x4.trans.shared.b16 {%0,%1,%2,%3},[%4];"
                    : "=r"(b[np][0]), "=r"(b[np][1]), "=r"(b[np][2]), "=r"(b[np][3])
                    : "r"(ad));
            }
            #pragma unroll
            for (int mt = 0; mt < 4; mt++)
                #pragma unroll
                for (int nt = 0; nt < 4; nt++) {
                    uint32_t b0 = b[nt >> 1][(nt & 1) * 2];
                    uint32_t b1 = b[nt >> 1][(nt & 1) * 2 + 1];
                    asm volatile(
                        "mma.sync.aligned.m16n8k16.row.col.f32.bf16.bf16.f32 "
                        "{%0,%1,%2,%3},{%4,%5,%6,%7},{%8,%9},{%0,%1,%2,%3};"
                        : "+f"(c[mt][nt][0]), "+f"(c[mt][nt][1]),
                          "+f"(c[mt][nt][2]), "+f"(c[mt][nt][3])
                        : "r"(a[mt][0]), "r"(a[mt][1]), "r"(a[mt][2]), "r"(a[mt][3]),
                          "r"(b0), "r"(b1));
                }
        }
        __syncthreads();
    }

    if (mode == 0) {
        #pragma unroll
        for (int mt = 0; mt < 4; mt++) {
            int r0 = brow + wm * 64 + mt * 16 + (lane >> 2);
            #pragma unroll
            for (int nt = 0; nt < 4; nt++) {
                int col = bcol + wn * 32 + nt * 8 + 2 * (lane & 3);
                __nv_bfloat162 v0 = __floats2bfloat162_rn(c[mt][nt][0], c[mt][nt][1]);
                __nv_bfloat162 v1 = __floats2bfloat162_rn(c[mt][nt][2], c[mt][nt][3]);
                *(__nv_bfloat162*)&C[(size_t)r0 * 1024 + col] = v0;
                *(__nv_bfloat162*)&C[(size_t)(r0 + 8) * 1024 + col] = v1;
            }
        }
        __threadfence();
        __syncthreads();
        if (tid == 0) atomicAdd(&g_mdone, 1);
    } else {
        #pragma unroll
        for (int mt = 0; mt < 4; mt++)
            #pragma unroll
            for (int half = 0; half < 2; half++) {
                int r = brow + wm * 64 + mt * 16 + (lane >> 2) + half * 8;
                float s = 0.f;
                #pragma unroll
                for (int nt = 0; nt < 4; nt++) {
                    int col = bcol + wn * 32 + nt * 8 + 2 * (lane & 3);
                    float d0 = c[mt][nt][half * 2 + 0] + bias[col];
                    float d1 = c[mt][nt][half * 2 + 1] + bias[col + 1];
                    if (mode == 2) {
                        __nv_bfloat162 xz =
                            *(const __nv_bfloat162*)&g_Zb[(size_t)r * 2048 + xoff + col];
                        float2 xf = __bfloat1622float2(xz);
                        d0 -= xf.x; d1 -= xf.y;
                    }
                    s += d0 * d0 + d1 * d1;
                }
                s += __shfl_xor_sync(0xffffffffu, s, 1);
                s += __shfl_xor_sync(0xffffffffu, s, 2);
                if ((lane & 3) == 0) atomicAdd(&R[r], s);
            }
    }
}

// ---------------- L4 per row (warp per row) ---------------------------------
__global__ void l4_kernel(const float* __restrict__ Y) {
    int w = (blockIdx.x * blockDim.x + threadIdx.x) >> 5;
    int lane = threadIdx.x & 31;
    const __nv_bfloat16* zr = &g_Zb[(size_t)w * 2048];
    float dot = 0.f;
    for (int k = lane * 4; k < 2048; k += 128) {
        uint2 u = *(const uint2*)&zr[k];
        float4 v = *(const float4*)&g_v[k];
        float2 a = __bfloat1622float2(*(__nv_bfloat162*)&u.x);
        float2 b = __bfloat1622float2(*(__nv_bfloat162*)&u.y);
        dot += a.x * v.x + a.y * v.y + b.x * v.z + b.y * v.w;
    }
    #pragma unroll
    for (int o = 16; o; o >>= 1) dot += __shfl_xor_sync(0xffffffffu, dot, o);
    if (lane == 0) {
        float L4 = 0.5f * (dot + g_c0[0]) - Y[w];
        g_L4sq[w] = L4 * L4;
    }
}

// ---------------- final scalar reduction (double) ---------------------------
__global__ void final_reduce_kernel(float* out) {
    __shared__ double sm[32];
    double s = 0.0;
    for (int r = threadIdx.x; r < NR; r += 1024) {
        double a = (double)g_row1[r], b = (double)g_row2[r], d = (double)g_row3[r];
        s += a * a + b * b + d * d + (double)g_L4sq[r];
    }
    #pragma unroll
    for (int o = 16; o; o >>= 1) s += __shfl_xor_sync(0xffffffffu, s, o);
    if ((threadIdx.x & 31) == 0) sm[threadIdx.x >> 5] = s;
    __syncthreads();
    if (threadIdx.x < 32) {
        double v = sm[threadIdx.x];
        #pragma unroll
        for (int o = 16; o; o >>= 1) v += __shfl_xor_sync(0xffffffffu, v, o);
        if (threadIdx.x == 0) out[0] = (float)v;
    }
}

// ---------------- launch -----------------------------------------------------
extern "C" void kernel_launch(void* const* d_in, const int* in_sizes, int n_in,
                              void* d_out, int out_size) {
    const float* X1   = (const float*)d_in[0];
    const float* X2   = (const float*)d_in[1];
    const float* Y    = (const float*)d_in[2];
    const float* w1hW = (const float*)d_in[3];
    const float* w1hb = (const float*)d_in[4];
    const float* w2hW = (const float*)d_in[5];
    const float* w2hb = (const float*)d_in[6];
    const float* wh1W = (const float*)d_in[7];
    const float* wh1b = (const float*)d_in[8];
    const float* wh2W = (const float*)d_in[9];
    const float* wh2b = (const float*)d_in[10];
    const float* whoW = (const float*)d_in[11];
    const float* whob = (const float*)d_in[12];

    static cudaStream_t sA = nullptr, sB = nullptr, sC = nullptr;
    static cudaEvent_t evStart = nullptr, evZ = nullptr, evB = nullptr,
                       evL4 = nullptr;
    if (sA == nullptr) {
        cudaStreamCreateWithFlags(&sA, cudaStreamNonBlocking);
        cudaStreamCreateWithFlags(&sB, cudaStreamNonBlocking);
        cudaStreamCreateWithFlags(&sC, cudaStreamNonBlocking);
        cudaEventCreateWithFlags(&evStart, cudaEventDisableTiming);
        cudaEventCreateWithFlags(&evZ, cudaEventDisableTiming);
        cudaEventCreateWithFlags(&evB, cudaEventDisableTiming);
        cudaEventCreateWithFlags(&evL4, cudaEventDisableTiming);
    }

    cudaEventRecord(evStart, 0);
    cudaStreamWaitEvent(sA, evStart, 0);
    cudaStreamWaitEvent(sB, evStart, 0);
    cudaStreamWaitEvent(sC, evStart, 0);

    // branch A: X -> Z conversion
    convz_kernel<<<4096, 256, 0, sA>>>(X1, X2);
    cudaEventRecord(evZ, sA);

    // branch B: counter/row zeroing + bias composition
    init_kernel<<<64, 256, 0, sB>>>(w1hb, w2hb, wh1b, wh2b);
    bcomp_kernel<<<dim3(4, 128, 2), 256, 0, sB>>>(w1hb, w2hb, wh2W, wh1W);
    cudaEventRecord(evB, sB);

    // branch C: v vector, then L4 (needs Z) — overlaps the merged GEMM
    vcomp_kernel<<<257, 256, 0, sC>>>(w1hW, w2hW, whoW, w1hb, w2hb, whob);
    cudaStreamWaitEvent(sC, evZ, 0);
    l4_kernel<<<NR / 8, 256, 0, sC>>>(Y);
    cudaEventRecord(evL4, sC);

    // main: weight convert, then ONE merged GEMM launch (M + L3 + X)
    convw_kernel<<<4096, 256>>>(w1hW, w2hW, wh1W, wh2W);
    cudaStreamWaitEvent(0, evZ, 0);
    cudaStreamWaitEvent(0, evB, 0);
    gemm_all<<<4224, 256>>>();

    cudaStreamWaitEvent(0, evL4, 0);
    final_reduce_kernel<<<1, 1024>>>((float*)d_out);
}

// round 15
// speedup vs baseline: 1.0157x; 1.0157x over previous
#include <cuda_runtime.h>
#include <cuda_bf16.h>
#include <cstdint>
#include <cstddef>

#define NR 16384
#define DX 1024
#define DH 2048
#define NTILES 4096

// ---------------- device scratch (no dynamic allocation allowed) -----------
__device__ __align__(16) __nv_bfloat16 g_Zb[(size_t)NR * 2048];     // [X1|X2]
__device__ __align__(16) __nv_bfloat16 g_Wst[(size_t)2048 * 2048];  // [W1h;-W2h]
__device__ __align__(16) __nv_bfloat16 g_W2hb[(size_t)1024 * 2048];
__device__ __align__(16) __nv_bfloat16 g_Wh1b[(size_t)2048 * 1024];
__device__ __align__(16) __nv_bfloat16 g_Wh2b[(size_t)2048 * 1024];
__device__ __align__(16) __nv_bfloat16 g_M12[(size_t)1024 * 1024];
__device__ __align__(16) __nv_bfloat16 g_M21[(size_t)1024 * 1024];
__device__ float g_b12[1024];
__device__ float g_b21[1024];
__device__ float g_db[2048];
__device__ float g_v[2048];
__device__ float g_c0[1];
__device__ float g_row1[NR];
__device__ float g_row2[NR];
__device__ float g_row3[NR];
__device__ float g_L4sq[NR];
__device__ int   g_tile;

// ---------------- helpers --------------------------------------------------
__device__ __forceinline__ uint32_t smem_u32(const void* p) {
    uint32_t a;
    asm("{ .reg .u64 t; cvta.to.shared.u64 t, %1; cvt.u32.u64 %0, t; }"
        : "=r"(a) : "l"(p));
    return a;
}
__device__ __forceinline__ void cp16(uint32_t dst, const void* src) {
    uint64_t g;
    asm("cvta.to.global.u64 %0, %1;" : "=l"(g) : "l"(src));
    asm volatile("cp.async.cg.shared.global [%0], [%1], 16;"
                 :: "r"(dst), "l"(g) : "memory");
}
#define CP_COMMIT asm volatile("cp.async.commit_group;" ::: "memory")
#define CP_WAIT(n) asm volatile("cp.async.wait_group %0;" :: "n"(n) : "memory")

// ---------------- converts / init ------------------------------------------
__global__ void convz_kernel(const float* __restrict__ X1,
                             const float* __restrict__ X2) {
    int i = blockIdx.x * blockDim.x + threadIdx.x;
    int stride = gridDim.x * blockDim.x;
    for (; i < NR * 256; i += stride) {
        int r = i >> 8, c = (i & 255) * 4;
        float4 a = __ldcs((const float4*)&X1[(size_t)r * 1024 + c]);
        float4 b = __ldcs((const float4*)&X2[(size_t)r * 1024 + c]);
        __nv_bfloat162 a0 = __floats2bfloat162_rn(a.x, a.y);
        __nv_bfloat162 a1 = __floats2bfloat162_rn(a.z, a.w);
        __nv_bfloat162 b0 = __floats2bfloat162_rn(b.x, b.y);
        __nv_bfloat162 b1 = __floats2bfloat162_rn(b.z, b.w);
        size_t o = (size_t)r * 2048 + c;
        __stcs((uint32_t*)&g_Zb[o],        *(uint32_t*)&a0);
        __stcs((uint32_t*)&g_Zb[o + 2],    *(uint32_t*)&a1);
        __stcs((uint32_t*)&g_Zb[o + 1024], *(uint32_t*)&b0);
        __stcs((uint32_t*)&g_Zb[o + 1026], *(uint32_t*)&b1);
    }
}

__global__ void convw_kernel(const float* __restrict__ w1hW,
                             const float* __restrict__ w2hW,
                             const float* __restrict__ wh1W,
                             const float* __restrict__ wh2W) {
    const int NW = DX * DH / 4;
    int i = blockIdx.x * blockDim.x + threadIdx.x;
    int stride = gridDim.x * blockDim.x;
    for (; i < 4 * NW; i += stride) {
        int sel = i / NW;
        int idx = (i - sel * NW) * 4;
        const float* src = (sel == 0) ? w1hW : (sel == 1) ? w2hW
                          : (sel == 2) ? wh1W : wh2W;
        float4 v = __ldcs((const float4*)&src[idx]);
        __nv_bfloat162 lo = __floats2bfloat162_rn(v.x, v.y);
        __nv_bfloat162 hi = __floats2bfloat162_rn(v.z, v.w);
        if (sel == 0) {
            *(uint32_t*)&g_Wst[idx]     = *(uint32_t*)&lo;
            *(uint32_t*)&g_Wst[idx + 2] = *(uint32_t*)&hi;
        } else if (sel == 1) {
            __nv_bfloat162 nlo = __floats2bfloat162_rn(-v.x, -v.y);
            __nv_bfloat162 nhi = __floats2bfloat162_rn(-v.z, -v.w);
            *(uint32_t*)&g_Wst[(size_t)1024 * 2048 + idx]     = *(uint32_t*)&nlo;
            *(uint32_t*)&g_Wst[(size_t)1024 * 2048 + idx + 2] = *(uint32_t*)&nhi;
            *(uint32_t*)&g_W2hb[idx]     = *(uint32_t*)&lo;
            *(uint32_t*)&g_W2hb[idx + 2] = *(uint32_t*)&hi;
        } else {
            __nv_bfloat16* dst = (sel == 2) ? g_Wh1b : g_Wh2b;
            *(uint32_t*)&dst[idx]     = *(uint32_t*)&lo;
            *(uint32_t*)&dst[idx + 2] = *(uint32_t*)&hi;
        }
    }
}

__global__ void init_kernel(const float* __restrict__ b1h,
                            const float* __restrict__ b2h,
                            const float* __restrict__ bh1,
                            const float* __restrict__ bh2) {
    int i = blockIdx.x * blockDim.x + threadIdx.x;
    if (i == 0) g_tile = 0;
    if (i < NR) { g_row1[i] = 0.f; g_row2[i] = 0.f; g_row3[i] = 0.f; }
    if (i < 2048) g_db[i] = b1h[i] - b2h[i];
    if (i < 1024) { g_b12[i] = bh2[i]; g_b21[i] = bh1[i]; }
}

__global__ void bcomp_kernel(const float* __restrict__ b1h,
                             const float* __restrict__ b2h,
                             const float* __restrict__ wh2W,
                             const float* __restrict__ wh1W) {
    const int sel = blockIdx.z;
    const float* bh = sel ? b2h : b1h;
    const float* W  = sel ? wh1W : wh2W;
    float* out = sel ? g_b21 : g_b12;
    int j = blockIdx.x * 256 + threadIdx.x;
    int k0 = blockIdx.y * 16;
    float s = 0.f;
    #pragma unroll
    for (int k = 0; k < 16; k++)
        s += bh[k0 + k] * W[(size_t)(k0 + k) * 1024 + j];
    atomicAdd(&out[j], s);
}

__global__ void vcomp_kernel(const float* __restrict__ W1h,
                             const float* __restrict__ W2h,
                             const float* __restrict__ who,
                             const float* __restrict__ b1h,
                             const float* __restrict__ b2h,
                             const float* __restrict__ whob) {
    int w = (blockIdx.x * blockDim.x + threadIdx.x) >> 5;
    int lane = threadIdx.x & 31;
    if (w > 2048) return;
    if (w == 2048) {
        float s = 0.f;
        for (int k = lane; k < 2048; k += 32)
            s += (b1h[k] + b2h[k]) * who[k];
        #pragma unroll
        for (int o = 16; o; o >>= 1) s += __shfl_xor_sync(0xffffffffu, s, o);
        if (lane == 0) g_c0[0] = s + whob[0];
        return;
    }
    const float* row = (w < 1024) ? &W1h[(size_t)w * 2048]
                                  : &W2h[(size_t)(w - 1024) * 2048];
    float s = 0.f;
    for (int k = lane; k < 2048; k += 32) s += row[k] * who[k];
    #pragma unroll
    for (int o = 16; o; o >>= 1) s += __shfl_xor_sync(0xffffffffu, s, o);
    if (lane == 0) g_v[w] = s;
}

// ---------------- M-GEMM (mma.sync bf16, 64x128x32) -------------------------
__launch_bounds__(256, 2)
__global__ void gemm_m() {
    const int z = blockIdx.z;
    const __nv_bfloat16* A = z ? g_W2hb : g_Wst;
    const __nv_bfloat16* B = z ? g_Wh1b : g_Wh2b;
    __nv_bfloat16* C = z ? g_M21 : g_M12;

    __shared__ __align__(16) __nv_bfloat16 smA[2][64][40];
    __shared__ __align__(16) __nv_bfloat16 smB[2][32][136];

    const int tid = threadIdx.x, lane = tid & 31, wid = tid >> 5;
    const int wm = wid >> 2, wn = wid & 3;
    const int brow = blockIdx.y * 64, bcol = blockIdx.x * 128;

    float c[2][4][4];
    #pragma unroll
    for (int i = 0; i < 2; i++)
        #pragma unroll
        for (int j = 0; j < 4; j++)
            #pragma unroll
            for (int k = 0; k < 4; k++) c[i][j][k] = 0.f;

    auto loadA = [&](int st, int k0) {
        int r = tid >> 2, kc = (tid & 3) * 8;
        cp16(smem_u32(&smA[st][r][kc]),
             &A[(size_t)(brow + r) * 2048 + k0 + kc]);
    };
    auto loadB = [&](int st, int k0) {
        #pragma unroll
        for (int i = 0; i < 2; i++) {
            int id = tid + i * 256;
            int r = id >> 4, nc = (id & 15) * 8;
            cp16(smem_u32(&smB[st][r][nc]),
                 &B[(size_t)(k0 + r) * 1024 + bcol + nc]);
        }
    };

    loadA(0, 0); loadB(0, 0); CP_COMMIT;
    for (int kt = 0; kt < 64; kt++) {
        const int cur = kt & 1, nxt = cur ^ 1;
        if (kt + 1 < 64) { loadA(nxt, (kt + 1) * 32); loadB(nxt, (kt + 1) * 32);
                           CP_COMMIT; CP_WAIT(1); }
        else             { CP_WAIT(0); }
        __syncthreads();

        #pragma unroll
        for (int ks = 0; ks < 32; ks += 16) {
            uint32_t a[2][4];
            #pragma unroll
            for (int mt = 0; mt < 2; mt++) {
                uint32_t ad = smem_u32(
                    &smA[cur][wm * 32 + mt * 16 + (lane & 15)][ks + (lane >> 4) * 8]);
                asm volatile(
                    "ldmatrix.sync.aligned.m8n8.x4.shared.b16 {%0,%1,%2,%3},[%4];"
                    : "=r"(a[mt][0]), "=r"(a[mt][1]), "=r"(a[mt][2]), "=r"(a[mt][3])
                    : "r"(ad));
            }
            uint32_t b[2][4];
            #pragma unroll
            for (int np = 0; np < 2; np++) {
                uint32_t ad = smem_u32(
                    &smB[cur][ks + (lane & 15)][wn * 32 + np * 16 + (lane >> 4) * 8]);
                asm volatile(
                    "ldmatrix.sync.aligned.m8n8.x4.trans.shared.b16 {%0,%1,%2,%3},[%4];"
                    : "=r"(b[np][0]), "=r"(b[np][1]), "=r"(b[np][2]), "=r"(b[np][3])
                    : "r"(ad));
            }
            #pragma unroll
            for (int mt = 0; mt < 2; mt++)
                #pragma unroll
                for (int nt = 0; nt < 4; nt++) {
                    uint32_t b0 = b[nt >> 1][(nt & 1) * 2];
                    uint32_t b1 = b[nt >> 1][(nt & 1) * 2 + 1];
                    asm volatile(
                        "mma.sync.aligned.m16n8k16.row.col.f32.bf16.bf16.f32 "
                        "{%0,%1,%2,%3},{%4,%5,%6,%7},{%8,%9},{%0,%1,%2,%3};"
                        : "+f"(c[mt][nt][0]), "+f"(c[mt][nt][1]),
                          "+f"(c[mt][nt][2]), "+f"(c[mt][nt][3])
                        : "r"(a[mt][0]), "r"(a[mt][1]), "r"(a[mt][2]), "r"(a[mt][3]),
                          "r"(b0), "r"(b1));
                }
        }
        __syncthreads();
    }

    #pragma unroll
    for (int mt = 0; mt < 2; mt++) {
        int r0 = brow + wm * 32 + mt * 16 + (lane >> 2);
        #pragma unroll
        for (int nt = 0; nt < 4; nt++) {
            int col = bcol + wn * 32 + nt * 8 + 2 * (lane & 3);
            __nv_bfloat162 v0 = __floats2bfloat162_rn(c[mt][nt][0], c[mt][nt][1]);
            __nv_bfloat162 v1 = __floats2bfloat162_rn(c[mt][nt][2], c[mt][nt][3]);
            *(__nv_bfloat162*)&C[(size_t)r0 * 1024 + col] = v0;
            *(__nv_bfloat162*)&C[(size_t)(r0 + 8) * 1024 + col] = v1;
        }
    }
}

// ---------------- persistent big GEMM: L3 + both X-GEMMs --------------------
// 296 resident CTAs work-steal NTILES tiles via g_tile.
// tiles 0..2047:    L3 (K=2048, B=Wst, bias=db)
// tiles 2048..4095: X  (K=1024, B=M12/M21, bias=b12/b21, subtract Z half)
__launch_bounds__(256, 2)
__global__ void gemm_big() {
    __shared__ __align__(16) __nv_bfloat16 smA[2][128][40];
    __shared__ __align__(16) __nv_bfloat16 smB[2][32][136];
    __shared__ int s_tile;

    const int tid = threadIdx.x, lane = tid & 31, wid = tid >> 5;
    const int wm = wid >> 2, wn = wid & 3;

    for (;;) {
        if (tid == 0) s_tile = atomicAdd(&g_tile, 1);
        __syncthreads();
        const int t0 = s_tile;
        if (t0 >= NTILES) return;
        __syncthreads();

        const __nv_bfloat16* A = g_Zb;
        const __nv_bfloat16* B;
        float* R;
        const float* bias;
        int K, LDB, aoff = 0, xoff = 0, isx, bx, by;
        if (t0 < 2048) {
            bx = t0 & 15; by = t0 >> 4;
            B = g_Wst; R = g_row3; bias = g_db;
            K = 2048; LDB = 2048; isx = 0;
        } else {
            int t = t0 - 2048;
            int zz = t >> 10; t &= 1023;
            bx = t & 7; by = t >> 3;
            B = zz ? g_M21 : g_M12; R = zz ? g_row2 : g_row1;
            bias = zz ? g_b21 : g_b12;
            aoff = zz * 1024; xoff = zz ? 0 : 1024;
            K = 1024; LDB = 1024; isx = 1;
        }
        const int brow = by * 128, bcol = bx * 128;

        float c[4][4][4];
        #pragma unroll
        for (int i = 0; i < 4; i++)
            #pragma unroll
            for (int j = 0; j < 4; j++)
                #pragma unroll
                for (int k = 0; k < 4; k++) c[i][j][k] = 0.f;

        auto loadA = [&](int st, int k0) {
            #pragma unroll
            for (int i = 0; i < 2; i++) {
                int id = tid + i * 256;
                int r = id >> 2, kc = (id & 3) * 8;
                cp16(smem_u32(&smA[st][r][kc]),
                     &A[(size_t)(brow + r) * 2048 + aoff + k0 + kc]);
            }
        };
        auto loadB = [&](int st, int k0) {
            #pragma unroll
            for (int i = 0; i < 2; i++) {
                int id = tid + i * 256;
                int r = id >> 4, nc = (id & 15) * 8;
                cp16(smem_u32(&smB[st][r][nc]),
                     &B[(size_t)(k0 + r) * LDB + bcol + nc]);
            }
        };

        loadA(0, 0); loadB(0, 0); CP_COMMIT;
        const int nk = K / 32;
        for (int kt = 0; kt < nk; kt++) {
            const int cur = kt & 1, nxt = cur ^ 1;
            if (kt + 1 < nk) { loadA(nxt, (kt + 1) * 32); loadB(nxt, (kt + 1) * 32);
                               CP_COMMIT; CP_WAIT(1); }
            else             { CP_WAIT(0); }
            __syncthreads();

            #pragma unroll
            for (int ks = 0; ks < 32; ks += 16) {
                uint32_t a[4][4];
                #pragma unroll
                for (int mt = 0; mt < 4; mt++) {
                    uint32_t ad = smem_u32(
                        &smA[cur][wm * 64 + mt * 16 + (lane & 15)]
                            [ks + (lane >> 4) * 8]);
                    asm volatile(
                        "ldmatrix.sync.aligned.m8n8.x4.shared.b16 {%0,%1,%2,%3},[%4];"
                        : "=r"(a[mt][0]), "=r"(a[mt][1]), "=r"(a[mt][2]), "=r"(a[mt][3])
                        : "r"(ad));
                }
                uint32_t b[2][4];
                #pragma unroll
                for (int np = 0; np < 2; np++) {
                    uint32_t ad = smem_u32(
                        &smB[cur][ks + (lane & 15)][wn * 32 + np * 16 + (lane >> 4) * 8]);
                    asm volatile(
                        "ldmatrix.sync.aligned.m8n8.x4.trans.shared.b16 {%0,%1,%2,%3},[%4];"
                        : "=r"(b[np][0]), "=r"(b[np][1]), "=r"(b[np][2]), "=r"(b[np][3])
                        : "r"(ad));
                }
                #pragma unroll
                for (int mt = 0; mt < 4; mt++)
                    #pragma unroll
                    for (int nt = 0; nt < 4; nt++) {
                        uint32_t b0 = b[nt >> 1][(nt & 1) * 2];
                        uint32_t b1 = b[nt >> 1][(nt & 1) * 2 + 1];
                        asm volatile(
                            "mma.sync.aligned.m16n8k16.row.col.f32.bf16.bf16.f32 "
                            "{%0,%1,%2,%3},{%4,%5,%6,%7},{%8,%9},{%0,%1,%2,%3};"
                            : "+f"(c[mt][nt][0]), "+f"(c[mt][nt][1]),
                              "+f"(c[mt][nt][2]), "+f"(c[mt][nt][3])
                            : "r"(a[mt][0]), "r"(a[mt][1]), "r"(a[mt][2]), "r"(a[mt][3]),
                              "r"(b0), "r"(b1));
                    }
            }
            __syncthreads();
        }

        #pragma unroll
        for (int mt = 0; mt < 4; mt++)
            #pragma unroll
            for (int half = 0; half < 2; half++) {
                int r = brow + wm * 64 + mt * 16 + (lane >> 2) + half * 8;
                float s = 0.f;
                #pragma unroll
                for (int nt = 0; nt < 4; nt++) {
                    int col = bcol + wn * 32 + nt * 8 + 2 * (lane & 3);
                    float d0 = c[mt][nt][half * 2 + 0] + bias[col];
                    float d1 = c[mt][nt][half * 2 + 1] + bias[col + 1];
                    if (isx) {
                        __nv_bfloat162 xz =
                            *(const __nv_bfloat162*)&g_Zb[(size_t)r * 2048 + xoff + col];
                        float2 xf = __bfloat1622float2(xz);
                        d0 -= xf.x; d1 -= xf.y;
                    }
                    s += d0 * d0 + d1 * d1;
                }
                s += __shfl_xor_sync(0xffffffffu, s, 1);
                s += __shfl_xor_sync(0xffffffffu, s, 2);
                if ((lane & 3) == 0) atomicAdd(&R[r], s);
            }
        __syncthreads();
    }
}

// ---------------- L4 per row (warp per row) ---------------------------------
__global__ void l4_kernel(const float* __restrict__ Y) {
    int w = (blockIdx.x * blockDim.x + threadIdx.x) >> 5;
    int lane = threadIdx.x & 31;
    const __nv_bfloat16* zr = &g_Zb[(size_t)w * 2048];
    float dot = 0.f;
    for (int k = lane * 4; k < 2048; k += 128) {
        uint2 u = *(const uint2*)&zr[k];
        float4 v = *(const float4*)&g_v[k];
        float2 a = __bfloat1622float2(*(__nv_bfloat162*)&u.x);
        float2 b = __bfloat1622float2(*(__nv_bfloat162*)&u.y);
        dot += a.x * v.x + a.y * v.y + b.x * v.z + b.y * v.w;
    }
    #pragma unroll
    for (int o = 16; o; o >>= 1) dot += __shfl_xor_sync(0xffffffffu, dot, o);
    if (lane == 0) {
        float L4 = 0.5f * (dot + g_c0[0]) - Y[w];
        g_L4sq[w] = L4 * L4;
    }
}

// ---------------- final scalar reduction (double) ---------------------------
__global__ void final_reduce_kernel(float* out) {
    __shared__ double sm[32];
    double s = 0.0;
    for (int r = threadIdx.x; r < NR; r += 1024) {
        double a = (double)g_row1[r], b = (double)g_row2[r], d = (double)g_row3[r];
        s += a * a + b * b + d * d + (double)g_L4sq[r];
    }
    #pragma unroll
    for (int o = 16; o; o >>= 1) s += __shfl_xor_sync(0xffffffffu, s, o);
    if ((threadIdx.x & 31) == 0) sm[threadIdx.x >> 5] = s;
    __syncthreads();
    if (threadIdx.x < 32) {
        double v = sm[threadIdx.x];
        #pragma unroll
        for (int o = 16; o; o >>= 1) v += __shfl_xor_sync(0xffffffffu, v, o);
        if (threadIdx.x == 0) out[0] = (float)v;
    }
}

// ---------------- launch -----------------------------------------------------
extern "C" void kernel_launch(void* const* d_in, const int* in_sizes, int n_in,
                              void* d_out, int out_size) {
    const float* X1   = (const float*)d_in[0];
    const float* X2   = (const float*)d_in[1];
    const float* Y    = (const float*)d_in[2];
    const float* w1hW = (const float*)d_in[3];
    const float* w1hb = (const float*)d_in[4];
    const float* w2hW = (const float*)d_in[5];
    const float* w2hb = (const float*)d_in[6];
    const float* wh1W = (const float*)d_in[7];
    const float* wh1b = (const float*)d_in[8];
    const float* wh2W = (const float*)d_in[9];
    const float* wh2b = (const float*)d_in[10];
    const float* whoW = (const float*)d_in[11];
    const float* whob = (const float*)d_in[12];

    static cudaStream_t sA = nullptr, sB = nullptr, sC = nullptr;
    static cudaEvent_t evStart = nullptr, evZ = nullptr, evB = nullptr,
                       evL4 = nullptr;
    if (sA == nullptr) {
        cudaStreamCreateWithFlags(&sA, cudaStreamNonBlocking);
        cudaStreamCreateWithFlags(&sB, cudaStreamNonBlocking);
        cudaStreamCreateWithFlags(&sC, cudaStreamNonBlocking);
        cudaEventCreateWithFlags(&evStart, cudaEventDisableTiming);
        cudaEventCreateWithFlags(&evZ, cudaEventDisableTiming);
        cudaEventCreateWithFlags(&evB, cudaEventDisableTiming);
        cudaEventCreateWithFlags(&evL4, cudaEventDisableTiming);
    }

    cudaEventRecord(evStart, 0);
    cudaStreamWaitEvent(sA, evStart, 0);
    cudaStreamWaitEvent(sB, evStart, 0);
    cudaStreamWaitEvent(sC, evStart, 0);

    // branch A: X -> Z conversion (overlaps convw + M-GEMM)
    convz_kernel<<<4096, 256, 0, sA>>>(X1, X2);
    cudaEventRecord(evZ, sA);

    // branch B: counter/row zeroing + bias composition
    init_kernel<<<64, 256, 0, sB>>>(w1hb, w2hb, wh1b, wh2b);
    bcomp_kernel<<<dim3(4, 128, 2), 256, 0, sB>>>(w1hb, w2hb, wh2W, wh1W);
    cudaEventRecord(evB, sB);

    // branch C: v vector, then L4 (needs Z) — overlaps the big GEMM
    vcomp_kernel<<<257, 256, 0, sC>>>(w1hW, w2hW, whoW, w1hb, w2hb, whob);
    cudaStreamWaitEvent(sC, evZ, 0);
    l4_kernel<<<NR / 8, 256, 0, sC>>>(Y);
    cudaEventRecord(evL4, sC);

    // main: weight convert -> M-GEMM (needs only weights; fills convz window)
    convw_kernel<<<4096, 256>>>(w1hW, w2hW, wh1W, wh2W);
    gemm_m<<<dim3(8, 16, 2), 256>>>();                 // M12, M21

    // join Z and bias branches, then persistent merged GEMM (L3 + L1 + L2)
    cudaStreamWaitEvent(0, evZ, 0);
    cudaStreamWaitEvent(0, evB, 0);
    gemm_big<<<296, 256>>>();

    cudaStreamWaitEvent(0, evL4, 0);
    final_reduce_kernel<<<1, 1024>>>((float*)d_out);
}

// round 17
// speedup vs baseline: 1.0298x; 1.0139x over previous
#include <cuda_runtime.h>
#include <cuda_bf16.h>
#include <cstdint>
#include <cstddef>

#define NR 16384
#define DX 1024
#define DH 2048

// ---------------- device scratch (no dynamic allocation allowed) -----------
__device__ __align__(16) __nv_bfloat16 g_Zb[(size_t)NR * 2048];     // [X1|X2]
__device__ __align__(16) __nv_bfloat16 g_Wst[(size_t)2048 * 2048];  // [W1h;-W2h]
__device__ __align__(16) __nv_bfloat16 g_W2hb[(size_t)1024 * 2048];
__device__ __align__(16) __nv_bfloat16 g_Wh1b[(size_t)2048 * 1024];
__device__ __align__(16) __nv_bfloat16 g_Wh2b[(size_t)2048 * 1024];
__device__ __align__(16) __nv_bfloat16 g_M12[(size_t)1024 * 1024];
__device__ __align__(16) __nv_bfloat16 g_M21[(size_t)1024 * 1024];
__device__ float g_b12[1024];
__device__ float g_b21[1024];
__device__ float g_db[2048];
__device__ float g_v[2048];
__device__ float g_c0[1];
__device__ float g_row1[NR];
__device__ float g_row2[NR];
__device__ float g_row3[NR];
__device__ float g_L4sq[NR];

// ---------------- helpers --------------------------------------------------
__device__ __forceinline__ uint32_t smem_u32(const void* p) {
    uint32_t a;
    asm("{ .reg .u64 t; cvta.to.shared.u64 t, %1; cvt.u32.u64 %0, t; }"
        : "=r"(a) : "l"(p));
    return a;
}
__device__ __forceinline__ void cp16(uint32_t dst, const void* src) {
    uint64_t g;
    asm("cvta.to.global.u64 %0, %1;" : "=l"(g) : "l"(src));
    asm volatile("cp.async.cg.shared.global [%0], [%1], 16;"
                 :: "r"(dst), "l"(g) : "memory");
}
#define CP_COMMIT asm volatile("cp.async.commit_group;" ::: "memory")
#define CP_WAIT(n) asm volatile("cp.async.wait_group %0;" :: "n"(n) : "memory")

// ---------------- converts / init ------------------------------------------
__global__ void convz_kernel(const float* __restrict__ X1,
                             const float* __restrict__ X2) {
    int i = blockIdx.x * blockDim.x + threadIdx.x;
    int stride = gridDim.x * blockDim.x;
    for (; i < NR * 256; i += stride) {
        int r = i >> 8, c = (i & 255) * 4;
        float4 a = __ldcs((const float4*)&X1[(size_t)r * 1024 + c]);
        float4 b = __ldcs((const float4*)&X2[(size_t)r * 1024 + c]);
        __nv_bfloat162 a0 = __floats2bfloat162_rn(a.x, a.y);
        __nv_bfloat162 a1 = __floats2bfloat162_rn(a.z, a.w);
        __nv_bfloat162 b0 = __floats2bfloat162_rn(b.x, b.y);
        __nv_bfloat162 b1 = __floats2bfloat162_rn(b.z, b.w);
        size_t o = (size_t)r * 2048 + c;
        __stcs((uint32_t*)&g_Zb[o],        *(uint32_t*)&a0);
        __stcs((uint32_t*)&g_Zb[o + 2],    *(uint32_t*)&a1);
        __stcs((uint32_t*)&g_Zb[o + 1024], *(uint32_t*)&b0);
        __stcs((uint32_t*)&g_Zb[o + 1026], *(uint32_t*)&b1);
    }
}

__global__ void convw_kernel(const float* __restrict__ w1hW,
                             const float* __restrict__ w2hW,
                             const float* __restrict__ wh1W,
                             const float* __restrict__ wh2W) {
    const int NW = DX * DH / 4;
    int i = blockIdx.x * blockDim.x + threadIdx.x;
    int stride = gridDim.x * blockDim.x;
    for (; i < 4 * NW; i += stride) {
        int sel = i / NW;
        int idx = (i - sel * NW) * 4;
        const float* src = (sel == 0) ? w1hW : (sel == 1) ? w2hW
                          : (sel == 2) ? wh1W : wh2W;
        float4 v = __ldcs((const float4*)&src[idx]);
        __nv_bfloat162 lo = __floats2bfloat162_rn(v.x, v.y);
        __nv_bfloat162 hi = __floats2bfloat162_rn(v.z, v.w);
        if (sel == 0) {
            *(uint32_t*)&g_Wst[idx]     = *(uint32_t*)&lo;
            *(uint32_t*)&g_Wst[idx + 2] = *(uint32_t*)&hi;
        } else if (sel == 1) {
            __nv_bfloat162 nlo = __floats2bfloat162_rn(-v.x, -v.y);
            __nv_bfloat162 nhi = __floats2bfloat162_rn(-v.z, -v.w);
            *(uint32_t*)&g_Wst[(size_t)1024 * 2048 + idx]     = *(uint32_t*)&nlo;
            *(uint32_t*)&g_Wst[(size_t)1024 * 2048 + idx + 2] = *(uint32_t*)&nhi;
            *(uint32_t*)&g_W2hb[idx]     = *(uint32_t*)&lo;
            *(uint32_t*)&g_W2hb[idx + 2] = *(uint32_t*)&hi;
        } else {
            __nv_bfloat16* dst = (sel == 2) ? g_Wh1b : g_Wh2b;
            *(uint32_t*)&dst[idx]     = *(uint32_t*)&lo;
            *(uint32_t*)&dst[idx + 2] = *(uint32_t*)&hi;
        }
    }
}

__global__ void init_kernel(const float* __restrict__ b1h,
                            const float* __restrict__ b2h,
                            const float* __restrict__ bh1,
                            const float* __restrict__ bh2) {
    int i = blockIdx.x * blockDim.x + threadIdx.x;
    if (i < NR) { g_row1[i] = 0.f; g_row2[i] = 0.f; g_row3[i] = 0.f; }
    if (i < 2048) g_db[i] = b1h[i] - b2h[i];
    if (i < 1024) { g_b12[i] = bh2[i]; g_b21[i] = bh1[i]; }
}

__global__ void bcomp_kernel(const float* __restrict__ b1h,
                             const float* __restrict__ b2h,
                             const float* __restrict__ wh2W,
                             const float* __restrict__ wh1W) {
    const int sel = blockIdx.z;
    const float* bh = sel ? b2h : b1h;
    const float* W  = sel ? wh1W : wh2W;
    float* out = sel ? g_b21 : g_b12;
    int j = blockIdx.x * 256 + threadIdx.x;
    int k0 = blockIdx.y * 16;
    float s = 0.f;
    #pragma unroll
    for (int k = 0; k < 16; k++)
        s += bh[k0 + k] * W[(size_t)(k0 + k) * 1024 + j];
    atomicAdd(&out[j], s);
}

__global__ void vcomp_kernel(const float* __restrict__ W1h,
                             const float* __restrict__ W2h,
                             const float* __restrict__ who,
                             const float* __restrict__ b1h,
                             const float* __restrict__ b2h,
                             const float* __restrict__ whob) {
    int w = (blockIdx.x * blockDim.x + threadIdx.x) >> 5;
    int lane = threadIdx.x & 31;
    if (w > 2048) return;
    if (w == 2048) {
        float s = 0.f;
        for (int k = lane; k < 2048; k += 32)
            s += (b1h[k] + b2h[k]) * who[k];
        #pragma unroll
        for (int o = 16; o; o >>= 1) s += __shfl_xor_sync(0xffffffffu, s, o);
        if (lane == 0) g_c0[0] = s + whob[0];
        return;
    }
    const float* row = (w < 1024) ? &W1h[(size_t)w * 2048]
                                  : &W2h[(size_t)(w - 1024) * 2048];
    float s = 0.f;
    for (int k = lane; k < 2048; k += 32) s += row[k] * who[k];
    #pragma unroll
    for (int o = 16; o; o >>= 1) s += __shfl_xor_sync(0xffffffffu, s, o);
    if (lane == 0) g_v[w] = s;
}

// ---------------- M-GEMM (mma.sync bf16, 64x128x32) -------------------------
__launch_bounds__(256, 2)
__global__ void gemm_m() {
    const int z = blockIdx.z;
    const __nv_bfloat16* A = z ? g_W2hb : g_Wst;
    const __nv_bfloat16* B = z ? g_Wh1b : g_Wh2b;
    __nv_bfloat16* C = z ? g_M21 : g_M12;

    __shared__ __align__(16) __nv_bfloat16 smA[2][64][40];
    __shared__ __align__(16) __nv_bfloat16 smB[2][32][136];

    const int tid = threadIdx.x, lane = tid & 31, wid = tid >> 5;
    const int wm = wid >> 2, wn = wid & 3;
    const int brow = blockIdx.y * 64, bcol = blockIdx.x * 128;

    float c[2][4][4];
    #pragma unroll
    for (int i = 0; i < 2; i++)
        #pragma unroll
        for (int j = 0; j < 4; j++)
            #pragma unroll
            for (int k = 0; k < 4; k++) c[i][j][k] = 0.f;

    auto loadA = [&](int st, int k0) {
        int r = tid >> 2, kc = (tid & 3) * 8;
        cp16(smem_u32(&smA[st][r][kc]),
             &A[(size_t)(brow + r) * 2048 + k0 + kc]);
    };
    auto loadB = [&](int st, int k0) {
        #pragma unroll
        for (int i = 0; i < 2; i++) {
            int id = tid + i * 256;
            int r = id >> 4, nc = (id & 15) * 8;
            cp16(smem_u32(&smB[st][r][nc]),
                 &B[(size_t)(k0 + r) * 1024 + bcol + nc]);
        }
    };

    loadA(0, 0); loadB(0, 0); CP_COMMIT;
    for (int kt = 0; kt < 64; kt++) {
        const int cur = kt & 1, nxt = cur ^ 1;
        if (kt + 1 < 64) { loadA(nxt, (kt + 1) * 32); loadB(nxt, (kt + 1) * 32);
                           CP_COMMIT; CP_WAIT(1); }
        else             { CP_WAIT(0); }
        __syncthreads();

        #pragma unroll
        for (int ks = 0; ks < 32; ks += 16) {
            uint32_t a[2][4];
            #pragma unroll
            for (int mt = 0; mt < 2; mt++) {
                uint32_t ad = smem_u32(
                    &smA[cur][wm * 32 + mt * 16 + (lane & 15)][ks + (lane >> 4) * 8]);
                asm volatile(
                    "ldmatrix.sync.aligned.m8n8.x4.shared.b16 {%0,%1,%2,%3},[%4];"
                    : "=r"(a[mt][0]), "=r"(a[mt][1]), "=r"(a[mt][2]), "=r"(a[mt][3])
                    : "r"(ad));
            }
            uint32_t b[2][4];
            #pragma unroll
            for (int np = 0; np < 2; np++) {
                uint32_t ad = smem_u32(
                    &smB[cur][ks + (lane & 15)][wn * 32 + np * 16 + (lane >> 4) * 8]);
                asm volatile(
                    "ldmatrix.sync.aligned.m8n8.x4.trans.shared.b16 {%0,%1,%2,%3},[%4];"
                    : "=r"(b[np][0]), "=r"(b[np][1]), "=r"(b[np][2]), "=r"(b[np][3])
                    : "r"(ad));
            }
            #pragma unroll
            for (int mt = 0; mt < 2; mt++)
                #pragma unroll
                for (int nt = 0; nt < 4; nt++) {
                    uint32_t b0 = b[nt >> 1][(nt & 1) * 2];
                    uint32_t b1 = b[nt >> 1][(nt & 1) * 2 + 1];
                    asm volatile(
                        "mma.sync.aligned.m16n8k16.row.col.f32.bf16.bf16.f32 "
                        "{%0,%1,%2,%3},{%4,%5,%6,%7},{%8,%9},{%0,%1,%2,%3};"
                        : "+f"(c[mt][nt][0]), "+f"(c[mt][nt][1]),
                          "+f"(c[mt][nt][2]), "+f"(c[mt][nt][3])
                        : "r"(a[mt][0]), "r"(a[mt][1]), "r"(a[mt][2]), "r"(a[mt][3]),
                          "r"(b0), "r"(b1));
                }
        }
        __syncthreads();
    }

    #pragma unroll
    for (int mt = 0; mt < 2; mt++) {
        int r0 = brow + wm * 32 + mt * 16 + (lane >> 2);
        #pragma unroll
        for (int nt = 0; nt < 4; nt++) {
            int col = bcol + wn * 32 + nt * 8 + 2 * (lane & 3);
            __nv_bfloat162 v0 = __floats2bfloat162_rn(c[mt][nt][0], c[mt][nt][1]);
            __nv_bfloat162 v1 = __floats2bfloat162_rn(c[mt][nt][2], c[mt][nt][3]);
            *(__nv_bfloat162*)&C[(size_t)r0 * 1024 + col] = v0;
            *(__nv_bfloat162*)&C[(size_t)(r0 + 8) * 1024 + col] = v1;
        }
    }
}

// ---------------- merged big GEMM: L3 + both X-GEMMs, one launch ------------
// grid (16, 128, 2). z=0: L3 tile (K=2048, B=Wst).   z=1: X-GEMMs
// (blockIdx.x>>3 selects zz; K=1024, B=M12/M21, subtract Z half).
__launch_bounds__(256, 2)
__global__ void gemm_big() {
    const int z = blockIdx.z;
    int bx = blockIdx.x;

    const __nv_bfloat16* B;
    float* R;
    const float* bias;
    int K, LDB, aoff, xoff, isx;
    if (z == 0) {
        B = g_Wst; R = g_row3; bias = g_db;
        K = 2048; LDB = 2048; aoff = 0; xoff = 0; isx = 0;
    } else {
        int zz = bx >> 3; bx &= 7;
        B = zz ? g_M21 : g_M12; R = zz ? g_row2 : g_row1;
        bias = zz ? g_b21 : g_b12;
        K = 1024; LDB = 1024; aoff = zz * 1024; xoff = zz ? 0 : 1024; isx = 1;
    }
    const __nv_bfloat16* A = g_Zb;

    __shared__ __align__(16) __nv_bfloat16 smA[2][128][40];
    __shared__ __align__(16) __nv_bfloat16 smB[2][32][136];

    const int tid = threadIdx.x, lane = tid & 31, wid = tid >> 5;
    const int wm = wid >> 2, wn = wid & 3;
    const int brow = blockIdx.y * 128, bcol = bx * 128;

    float c[4][4][4];
    #pragma unroll
    for (int i = 0; i < 4; i++)
        #pragma unroll
        for (int j = 0; j < 4; j++)
            #pragma unroll
            for (int k = 0; k < 4; k++) c[i][j][k] = 0.f;

    auto loadA = [&](int st, int k0) {
        #pragma unroll
        for (int i = 0; i < 2; i++) {
            int id = tid + i * 256;
            int r = id >> 2, kc = (id & 3) * 8;
            cp16(smem_u32(&smA[st][r][kc]),
                 &A[(size_t)(brow + r) * 2048 + aoff + k0 + kc]);
        }
    };
    auto loadB = [&](int st, int k0) {
        #pragma unroll
        for (int i = 0; i < 2; i++) {
            int id = tid + i * 256;
            int r = id >> 4, nc = (id & 15) * 8;
            cp16(smem_u32(&smB[st][r][nc]),
                 &B[(size_t)(k0 + r) * LDB + bcol + nc]);
        }
    };

    loadA(0, 0); loadB(0, 0); CP_COMMIT;
    const int nk = K / 32;
    for (int kt = 0; kt < nk; kt++) {
        const int cur = kt & 1, nxt = cur ^ 1;
        if (kt + 1 < nk) { loadA(nxt, (kt + 1) * 32); loadB(nxt, (kt + 1) * 32);
                           CP_COMMIT; CP_WAIT(1); }
        else             { CP_WAIT(0); }
        __syncthreads();

        #pragma unroll
        for (int ks = 0; ks < 32; ks += 16) {
            uint32_t a[4][4];
            #pragma unroll
            for (int mt = 0; mt < 4; mt++) {
                uint32_t ad = smem_u32(
                    &smA[cur][wm * 64 + mt * 16 + (lane & 15)][ks + (lane >> 4) * 8]);
                asm volatile(
                    "ldmatrix.sync.aligned.m8n8.x4.shared.b16 {%0,%1,%2,%3},[%4];"
                    : "=r"(a[mt][0]), "=r"(a[mt][1]), "=r"(a[mt][2]), "=r"(a[mt][3])
                    : "r"(ad));
            }
            uint32_t b[2][4];
            #pragma unroll
            for (int np = 0; np < 2; np++) {
                uint32_t ad = smem_u32(
                    &smB[cur][ks + (lane & 15)][wn * 32 + np * 16 + (lane >> 4) * 8]);
                asm volatile(
                    "ldmatrix.sync.aligned.m8n8.x4.trans.shared.b16 {%0,%1,%2,%3},[%4];"
                    : "=r"(b[np][0]), "=r"(b[np][1]), "=r"(b[np][2]), "=r"(b[np][3])
                    : "r"(ad));
            }
            #pragma unroll
            for (int mt = 0; mt < 4; mt++)
                #pragma unroll
                for (int nt = 0; nt < 4; nt++) {
                    uint32_t b0 = b[nt >> 1][(nt & 1) * 2];
                    uint32_t b1 = b[nt >> 1][(nt & 1) * 2 + 1];
                    asm volatile(
                        "mma.sync.aligned.m16n8k16.row.col.f32.bf16.bf16.f32 "
                        "{%0,%1,%2,%3},{%4,%5,%6,%7},{%8,%9},{%0,%1,%2,%3};"
                        : "+f"(c[mt][nt][0]), "+f"(c[mt][nt][1]),
                          "+f"(c[mt][nt][2]), "+f"(c[mt][nt][3])
                        : "r"(a[mt][0]), "r"(a[mt][1]), "r"(a[mt][2]), "r"(a[mt][3]),
                          "r"(b0), "r"(b1));
                }
        }
        __syncthreads();
    }

    #pragma unroll
    for (int mt = 0; mt < 4; mt++)
        #pragma unroll
        for (int half = 0; half < 2; half++) {
            int r = brow + wm * 64 + mt * 16 + (lane >> 2) + half * 8;
            float s = 0.f;
            #pragma unroll
            for (int nt = 0; nt < 4; nt++) {
                int col = bcol + wn * 32 + nt * 8 + 2 * (lane & 3);
                float d0 = c[mt][nt][half * 2 + 0] + bias[col];
                float d1 = c[mt][nt][half * 2 + 1] + bias[col + 1];
                if (isx) {
                    __nv_bfloat162 xz =
                        *(const __nv_bfloat162*)&g_Zb[(size_t)r * 2048 + xoff + col];
                    float2 xf = __bfloat1622float2(xz);
                    d0 -= xf.x; d1 -= xf.y;
                }
                s += d0 * d0 + d1 * d1;
            }
            s += __shfl_xor_sync(0xffffffffu, s, 1);
            s += __shfl_xor_sync(0xffffffffu, s, 2);
            if ((lane & 3) == 0) atomicAdd(&R[r], s);
        }
}

// ---------------- L4 per row (warp per row) ---------------------------------
__global__ void l4_kernel(const float* __restrict__ Y) {
    int w = (blockIdx.x * blockDim.x + threadIdx.x) >> 5;
    int lane = threadIdx.x & 31;
    const __nv_bfloat16* zr = &g_Zb[(size_t)w * 2048];
    float dot = 0.f;
    for (int k = lane * 4; k < 2048; k += 128) {
        uint2 u = *(const uint2*)&zr[k];
        float4 v = *(const float4*)&g_v[k];
        float2 a = __bfloat1622float2(*(__nv_bfloat162*)&u.x);
        float2 b = __bfloat1622float2(*(__nv_bfloat162*)&u.y);
        dot += a.x * v.x + a.y * v.y + b.x * v.z + b.y * v.w;
    }
    #pragma unroll
    for (int o = 16; o; o >>= 1) dot += __shfl_xor_sync(0xffffffffu, dot, o);
    if (lane == 0) {
        float L4 = 0.5f * (dot + g_c0[0]) - Y[w];
        g_L4sq[w] = L4 * L4;
    }
}

// ---------------- final scalar reduction (double) ---------------------------
__global__ void final_reduce_kernel(float* out) {
    __shared__ double sm[32];
    double s = 0.0;
    for (int r = threadIdx.x; r < NR; r += 1024) {
        double a = (double)g_row1[r], b = (double)g_row2[r], d = (double)g_row3[r];
        s += a * a + b * b + d * d + (double)g_L4sq[r];
    }
    #pragma unroll
    for (int o = 16; o; o >>= 1) s += __shfl_xor_sync(0xffffffffu, s, o);
    if ((threadIdx.x & 31) == 0) sm[threadIdx.x >> 5] = s;
    __syncthreads();
    if (threadIdx.x < 32) {
        double v = sm[threadIdx.x];
        #pragma unroll
        for (int o = 16; o; o >>= 1) v += __shfl_xor_sync(0xffffffffu, v, o);
        if (threadIdx.x == 0) out[0] = (float)v;
    }
}

// ---------------- launch -----------------------------------------------------
extern "C" void kernel_launch(void* const* d_in, const int* in_sizes, int n_in,
                              void* d_out, int out_size) {
    const float* X1   = (const float*)d_in[0];
    const float* X2   = (const float*)d_in[1];
    const float* Y    = (const float*)d_in[2];
    const float* w1hW = (const float*)d_in[3];
    const float* w1hb = (const float*)d_in[4];
    const float* w2hW = (const float*)d_in[5];
    const float* w2hb = (const float*)d_in[6];
    const float* wh1W = (const float*)d_in[7];
    const float* wh1b = (const float*)d_in[8];
    const float* wh2W = (const float*)d_in[9];
    const float* wh2b = (const float*)d_in[10];
    const float* whoW = (const float*)d_in[11];
    const float* whob = (const float*)d_in[12];

    static cudaStream_t sA = nullptr, sB = nullptr, sC = nullptr;
    static cudaEvent_t evStart = nullptr, evZ = nullptr, evB = nullptr,
                       evL4 = nullptr;
    if (sA == nullptr) {
        cudaStreamCreateWithFlags(&sA, cudaStreamNonBlocking);
        cudaStreamCreateWithFlags(&sB, cudaStreamNonBlocking);
        cudaStreamCreateWithFlags(&sC, cudaStreamNonBlocking);
        cudaEventCreateWithFlags(&evStart, cudaEventDisableTiming);
        cudaEventCreateWithFlags(&evZ, cudaEventDisableTiming);
        cudaEventCreateWithFlags(&evB, cudaEventDisableTiming);
        cudaEventCreateWithFlags(&evL4, cudaEventDisableTiming);
    }

    cudaEventRecord(evStart, 0);
    cudaStreamWaitEvent(sA, evStart, 0);
    cudaStreamWaitEvent(sB, evStart, 0);
    cudaStreamWaitEvent(sC, evStart, 0);

    // branch A: X -> Z conversion (overlaps convw + M-GEMM)
    convz_kernel<<<4096, 256, 0, sA>>>(X1, X2);
    cudaEventRecord(evZ, sA);

    // branch B: row zeroing + bias composition
    init_kernel<<<64, 256, 0, sB>>>(w1hb, w2hb, wh1b, wh2b);
    bcomp_kernel<<<dim3(4, 128, 2), 256, 0, sB>>>(w1hb, w2hb, wh2W, wh1W);
    cudaEventRecord(evB, sB);

    // branch C: v vector, then L4 (needs Z) — overlaps the big GEMM
    vcomp_kernel<<<257, 256, 0, sC>>>(w1hW, w2hW, whoW, w1hb, w2hb, whob);
    cudaStreamWaitEvent(sC, evZ, 0);
    l4_kernel<<<NR / 8, 256, 0, sC>>>(Y);
    cudaEventRecord(evL4, sC);

    // main: weight convert -> M-GEMMs (need only weights; fills convz window)
    convw_kernel<<<4096, 256>>>(w1hW, w2hW, wh1W, wh2W);
    gemm_m<<<dim3(8, 16, 2), 256>>>();                 // M12, M21

    // join Z and bias branches, then the single merged GEMM
    cudaStreamWaitEvent(0, evZ, 0);
    cudaStreamWaitEvent(0, evB, 0);
    gemm_big<<<dim3(16, 128, 2), 256>>>();             // L3 + L1 + L2

    cudaStreamWaitEvent(0, evL4, 0);
    final_reduce_kernel<<<1, 1024>>>((float*)d_out);
}